// round 9
// baseline (speedup 1.0000x reference)
#include <cuda_runtime.h>
#include <cuda_bf16.h>
#include <math.h>
#include <stdint.h>

// Problem constants
#define T_TOK   8192
#define DIMM    2048
#define NH      16
#define NKV     8
#define HD      128
#define SEQ     1024
#define BATCH   8

// ---------------- scratch (device globals) ----------------
__device__ float g_q[T_TOK * (size_t)(NH * HD)];     // 8192 x 2048
__device__ float g_k[T_TOK * (size_t)(NKV * HD)];    // 8192 x 1024
__device__ float g_v[T_TOK * (size_t)(NKV * HD)];    // 8192 x 1024
__device__ float g_attn[T_TOK * (size_t)(NH * HD)];  // 8192 x 2048
__device__ float g_cos[SEQ * 64];
__device__ float g_sin[SEQ * 64];

__device__ __forceinline__ uint32_t f2tf(float x) {
    uint32_t r;
    asm("cvt.rna.tf32.f32 %0, %1;" : "=r"(r) : "f"(x));
    return r;
}

__device__ __forceinline__ void mma_tf32(float* c,
                                         uint32_t a0, uint32_t a1, uint32_t a2, uint32_t a3,
                                         uint32_t b0, uint32_t b1) {
    asm volatile(
        "mma.sync.aligned.m16n8k8.row.col.f32.tf32.tf32.f32 "
        "{%0,%1,%2,%3}, {%4,%5,%6,%7}, {%8,%9}, {%0,%1,%2,%3};\n"
        : "+f"(c[0]), "+f"(c[1]), "+f"(c[2]), "+f"(c[3])
        : "r"(a0), "r"(a1), "r"(a2), "r"(a3), "r"(b0), "r"(b1));
}

__device__ __forceinline__ void cp_async16(uint32_t smem_addr, const void* gptr) {
    asm volatile("cp.async.cg.shared.global [%0], [%1], 16;\n" ::
                 "r"(smem_addr), "l"(gptr));
}
__device__ __forceinline__ void cp_async_commit() {
    asm volatile("cp.async.commit_group;\n" ::: "memory");
}
__device__ __forceinline__ void cp_async_wait_all() {
    asm volatile("cp.async.wait_group 0;\n" ::: "memory");
}

// ---------------- RoPE table ----------------
__global__ void rope_table_kernel() {
    int idx = blockIdx.x * blockDim.x + threadIdx.x;
    if (idx >= SEQ * 64) return;
    int pos = idx >> 6;
    int f = idx & 63;
    double inv = pow(10000.0, -(double)f / 64.0);
    double ang = (double)pos * inv;
    g_cos[idx] = (float)cos(ang);
    g_sin[idx] = (float)sin(ang);
}

// ---------------- RoPE apply (optionally RNA-round output to tf32 grid) ----------------
__global__ void rope_apply_kernel(float* __restrict__ buf, const int* __restrict__ positions,
                                  int heads, int round_tf32) {
    int t = blockIdx.x;
    int pos = positions[t];
    int npairs = heads * 64;
    for (int i = threadIdx.x; i < npairs; i += blockDim.x) {
        int h = i >> 6;
        int f = i & 63;
        float c = g_cos[pos * 64 + f];
        float s = g_sin[pos * 64 + f];
        float* p = buf + (size_t)t * (heads * HD) + h * HD + 2 * f;
        float xr = p[0], xi = p[1];
        float o0 = xr * c - xi * s;
        float o1 = xr * s + xi * c;
        if (round_tf32) {
            o0 = __uint_as_float(f2tf(o0));
            o1 = __uint_as_float(f2tf(o1));
        }
        p[0] = o0;
        p[1] = o1;
    }
}

// ---------------- round V buffer to tf32 grid (RNA) ----------------
__global__ void round_v_kernel(float* __restrict__ v) {
    // 8192*1024 floats = 2097152 float4
    int idx = blockIdx.x * blockDim.x + threadIdx.x;
    float4* p = (float4*)v;
#pragma unroll
    for (int j = 0; j < 4; j++) {
        int i = idx + j * 524288;
        float4 t = p[i];
        t.x = __uint_as_float(f2tf(t.x));
        t.y = __uint_as_float(f2tf(t.y));
        t.z = __uint_as_float(f2tf(t.z));
        t.w = __uint_as_float(f2tf(t.w));
        p[i] = t;
    }
}

// ---------------- TF32 tensor-core GEMM (validated R4) ----------------
#define GST 136

__global__ __launch_bounds__(256, 2) void tf32_gemm(const float* __restrict__ A,
                                                    const float* __restrict__ B,
                                                    float* __restrict__ C,
                                                    int M, int N, int K) {
    __shared__ uint32_t As[2][16][GST];
    __shared__ uint32_t Bs[2][16][GST];

    int tid = threadIdx.x;
    int warp = tid >> 5, lane = tid & 31;
    int wy = warp >> 2, wx = warp & 3;
    int group = lane >> 2, tg = lane & 3;
    int bm = blockIdx.y * 128, bn = blockIdx.x * 128;

    int am = tid & 127;
    int ak = (tid >> 7) * 4;
    int bk = tid >> 5;
    int bn4 = (tid & 31) * 4;

    const float* Abase = A + (size_t)(bm + am) * K;
    const float* Bbase = B + bn + bn4;

    float4 av0, av1, bv0, bv1;
    av0 = *(const float4*)(Abase + ak);
    av1 = *(const float4*)(Abase + ak + 8);
    bv0 = *(const float4*)(Bbase + (size_t)bk * N);
    bv1 = *(const float4*)(Bbase + (size_t)(bk + 8) * N);

    float acc[4][4][4];
#pragma unroll
    for (int mt = 0; mt < 4; mt++)
#pragma unroll
        for (int nt = 0; nt < 4; nt++)
#pragma unroll
            for (int r = 0; r < 4; r++) acc[mt][nt][r] = 0.f;

    As[0][ak + 0][am] = f2tf(av0.x);
    As[0][ak + 1][am] = f2tf(av0.y);
    As[0][ak + 2][am] = f2tf(av0.z);
    As[0][ak + 3][am] = f2tf(av0.w);
    As[0][ak + 8][am] = f2tf(av1.x);
    As[0][ak + 9][am] = f2tf(av1.y);
    As[0][ak + 10][am] = f2tf(av1.z);
    As[0][ak + 11][am] = f2tf(av1.w);
    {
        uint4 t0 = make_uint4(f2tf(bv0.x), f2tf(bv0.y), f2tf(bv0.z), f2tf(bv0.w));
        uint4 t1 = make_uint4(f2tf(bv1.x), f2tf(bv1.y), f2tf(bv1.z), f2tf(bv1.w));
        *(uint4*)&Bs[0][bk][bn4] = t0;
        *(uint4*)&Bs[0][bk + 8][bn4] = t1;
    }
    __syncthreads();

    int NT = K >> 4;
    int p = 0;
    for (int kt = 0; kt < NT; kt++) {
        if (kt + 1 < NT) {
            const float* Ap = Abase + (kt + 1) * 16;
            av0 = *(const float4*)(Ap + ak);
            av1 = *(const float4*)(Ap + ak + 8);
            const float* Bp = Bbase + (size_t)(kt + 1) * 16 * N;
            bv0 = *(const float4*)(Bp + (size_t)bk * N);
            bv1 = *(const float4*)(Bp + (size_t)(bk + 8) * N);
        }

#pragma unroll
        for (int ks = 0; ks < 2; ks++) {
            int k0 = ks * 8;
            uint32_t afr[4][4], bfr[4][2];
#pragma unroll
            for (int nt = 0; nt < 4; nt++) {
                int nb = wx * 32 + nt * 8 + group;
                bfr[nt][0] = Bs[p][k0 + tg][nb];
                bfr[nt][1] = Bs[p][k0 + tg + 4][nb];
            }
#pragma unroll
            for (int mt = 0; mt < 4; mt++) {
                int mb = wy * 64 + mt * 16 + group;
                afr[mt][0] = As[p][k0 + tg][mb];
                afr[mt][1] = As[p][k0 + tg][mb + 8];
                afr[mt][2] = As[p][k0 + tg + 4][mb];
                afr[mt][3] = As[p][k0 + tg + 4][mb + 8];
            }
#pragma unroll
            for (int mt = 0; mt < 4; mt++)
#pragma unroll
                for (int nt = 0; nt < 4; nt++)
                    mma_tf32(acc[mt][nt], afr[mt][0], afr[mt][1], afr[mt][2], afr[mt][3],
                             bfr[nt][0], bfr[nt][1]);
        }

        if (kt + 1 < NT) {
            int q = p ^ 1;
            As[q][ak + 0][am] = f2tf(av0.x);
            As[q][ak + 1][am] = f2tf(av0.y);
            As[q][ak + 2][am] = f2tf(av0.z);
            As[q][ak + 3][am] = f2tf(av0.w);
            As[q][ak + 8][am] = f2tf(av1.x);
            As[q][ak + 9][am] = f2tf(av1.y);
            As[q][ak + 10][am] = f2tf(av1.z);
            As[q][ak + 11][am] = f2tf(av1.w);
            uint4 t0 = make_uint4(f2tf(bv0.x), f2tf(bv0.y), f2tf(bv0.z), f2tf(bv0.w));
            uint4 t1 = make_uint4(f2tf(bv1.x), f2tf(bv1.y), f2tf(bv1.z), f2tf(bv1.w));
            *(uint4*)&Bs[q][bk][bn4] = t0;
            *(uint4*)&Bs[q][bk + 8][bn4] = t1;
        }
        __syncthreads();
        p ^= 1;
    }

#pragma unroll
    for (int mt = 0; mt < 4; mt++) {
#pragma unroll
        for (int nt = 0; nt < 4; nt++) {
            int row = bm + wy * 64 + mt * 16 + group;
            int col = bn + wx * 32 + nt * 8 + tg * 2;
            float2 v01 = make_float2(acc[mt][nt][0], acc[mt][nt][1]);
            float2 v23 = make_float2(acc[mt][nt][2], acc[mt][nt][3]);
            *(float2*)(C + (size_t)row * N + col) = v01;
            *(float2*)(C + (size_t)(row + 8) * N + col) = v23;
        }
    }
}

// ---------------- Flash attention, tf32 mma, cp.async double-buffered K/V, Q in regs ----------------
// Q tile 128 x 128, key tile 64. 256 threads = 8 warps; warp w owns q rows [16w,16w+16).
// K/V pre-rounded to tf32 grid in gmem -> cp.async 16B straight into smem, no conversion.
// Q held in registers (64/thread, scaled+rounded at load).
// smem: KV double buffer 2 x (64x132 K + 64x132 V) + P 128x68  (~170 KB, 1 CTA/SM).
#define AT_KST 132
#define AT_PST 68
#define KVBUF  (64 * AT_KST)                      // one K or V tile in words
#define AT_SMEM_WORDS (4 * KVBUF + 128 * AT_PST)  // 42496 words = 166 KB

__global__ __launch_bounds__(256, 1) void attn5_kernel(const float* __restrict__ qb,
                                                       const float* __restrict__ kb,
                                                       const float* __restrict__ vb,
                                                       float* __restrict__ ob) {
    extern __shared__ uint32_t smw[];
    // buffers: [stage p][K then V]
    uint32_t* Ps = smw + 4 * KVBUF;           // [128][68]

    const float scale = 0.08838834764831845f;
    int qt = 7 - blockIdx.x;                  // heavy tiles first
    int bh = blockIdx.y;
    int b = bh >> 4;
    int h = bh & 15;
    int kvh = h >> 1;

    int tid = threadIdx.x;
    int warp = tid >> 5, lane = tid & 31;
    int group = lane >> 2, tg = lane & 3;
    int mrow0 = warp * 16;

    // staging map for cp.async (8 x 16B per thread per K/V tile)
    int sr = tid >> 5;            // base row (advance by 8)
    int sc4 = (tid & 31) * 4;     // float offset within row
    size_t kvstride = (size_t)(NKV * HD);
    const float* kvb_base_k = kb + (size_t)((b << 10)) * kvstride + (kvh << 7) + sc4;
    const float* kvb_base_v = vb + (size_t)((b << 10)) * kvstride + (kvh << 7) + sc4;

    uint32_t smem_base_u32;
    {
        void* gp = (void*)smw;
        smem_base_u32 = (uint32_t)__cvta_generic_to_shared(gp);
    }

    int ntiles = 2 * qt + 2;

    // ---- prologue: stage tile 0 into buffer 0 ----
    {
        int r0 = 0 * 64;
#pragma unroll
        for (int j = 0; j < 8; j++) {
            int r = sr + j * 8;
            uint32_t kdst = smem_base_u32 + (0 * 2 * KVBUF + r * AT_KST + sc4) * 4;
            uint32_t vdst = smem_base_u32 + ((0 * 2 + 1) * KVBUF + r * AT_KST + sc4) * 4;
            cp_async16(kdst, kvb_base_k + (size_t)(r0 + r) * kvstride);
            cp_async16(vdst, kvb_base_v + (size_t)(r0 + r) * kvstride);
        }
        cp_async_commit();
    }

    // ---- load Q into registers (scaled, RNA-rounded) ----
    // qA[half*32+m] = Q[row_half][tg + 4m]
    uint32_t qA[64];
    {
        int tok0 = (b << 10) + (qt << 7) + mrow0 + group;
        const float* q0 = qb + (size_t)tok0 * (NH * HD) + (h << 7) + tg;
        const float* q1 = q0 + 8 * (size_t)(NH * HD);
#pragma unroll
        for (int m = 0; m < 32; m++) {
            qA[m] = f2tf(q0[4 * m] * scale);
            qA[32 + m] = f2tf(q1[4 * m] * scale);
        }
    }

    float Oacc[16][4];
#pragma unroll
    for (int ot = 0; ot < 16; ot++)
#pragma unroll
        for (int r = 0; r < 4; r++) Oacc[ot][r] = 0.f;
    float mrow[2] = {-INFINITY, -INFINITY};
    float lrow[2] = {0.f, 0.f};

    for (int kt = 0; kt < ntiles; kt++) {
        int p = kt & 1;
        cp_async_wait_all();
        __syncthreads();   // staged data visible; all warps done with buffer p^1 from kt-1

        // prefetch kt+1 into the other buffer
        if (kt + 1 < ntiles) {
            int q = p ^ 1;
            int r0 = (kt + 1) * 64;
#pragma unroll
            for (int j = 0; j < 8; j++) {
                int r = sr + j * 8;
                uint32_t kdst = smem_base_u32 + (q * 2 * KVBUF + r * AT_KST + sc4) * 4;
                uint32_t vdst = smem_base_u32 + ((q * 2 + 1) * KVBUF + r * AT_KST + sc4) * 4;
                cp_async16(kdst, kvb_base_k + (size_t)(r0 + r) * kvstride);
                cp_async16(vdst, kvb_base_v + (size_t)(r0 + r) * kvstride);
            }
            cp_async_commit();
        }

        const uint32_t* Ksp = smw + p * 2 * KVBUF;
        const uint32_t* Vsp = Ksp + KVBUF;

        bool active = (kt << 6) <= (qt << 7) + mrow0 + 15;
        if (active) {
            // ---- scores: S(16x64) ----
            float sacc[8][4];
#pragma unroll
            for (int nt = 0; nt < 8; nt++)
#pragma unroll
                for (int r = 0; r < 4; r++) sacc[nt][r] = 0.f;

#pragma unroll 4
            for (int ks = 0; ks < 16; ks++) {
                uint32_t a0 = qA[2 * ks];
                uint32_t a1 = qA[32 + 2 * ks];
                uint32_t a2 = qA[2 * ks + 1];
                uint32_t a3 = qA[32 + 2 * ks + 1];
                int k0 = ks * 8;
#pragma unroll
                for (int nt = 0; nt < 8; nt++) {
                    const uint32_t* kr = Ksp + (nt * 8 + group) * AT_KST + k0 + tg;
                    mma_tf32(sacc[nt], a0, a1, a2, a3, kr[0], kr[4]);
                }
            }

            // causal mask (diagonal super-tiles only)
            if (kt >= 2 * qt) {
                int qp = (qt << 7) + mrow0 + group;
#pragma unroll
                for (int nt = 0; nt < 8; nt++) {
                    int kp = (kt << 6) + nt * 8 + 2 * tg;
                    if (kp > qp) sacc[nt][0] = -INFINITY;
                    if (kp + 1 > qp) sacc[nt][1] = -INFINITY;
                    if (kp > qp + 8) sacc[nt][2] = -INFINITY;
                    if (kp + 1 > qp + 8) sacc[nt][3] = -INFINITY;
                }
            }

            // ---- online softmax (fp32, warp-private rows) + write P (tf32) ----
#pragma unroll
            for (int hf = 0; hf < 2; hf++) {
                float tm = -INFINITY;
#pragma unroll
                for (int nt = 0; nt < 8; nt++) {
                    tm = fmaxf(tm, sacc[nt][2 * hf]);
                    tm = fmaxf(tm, sacc[nt][2 * hf + 1]);
                }
                tm = fmaxf(tm, __shfl_xor_sync(0xffffffffu, tm, 1));
                tm = fmaxf(tm, __shfl_xor_sync(0xffffffffu, tm, 2));
                float mn = fmaxf(mrow[hf], tm);
                float corr = __expf(mrow[hf] - mn);
                float ps = 0.f;
                int row = mrow0 + group + hf * 8;
#pragma unroll
                for (int nt = 0; nt < 8; nt++) {
                    float p0 = __expf(sacc[nt][2 * hf] - mn);
                    float p1 = __expf(sacc[nt][2 * hf + 1] - mn);
                    ps += p0 + p1;
                    *(uint2*)&Ps[row * AT_PST + nt * 8 + 2 * tg] = make_uint2(f2tf(p0), f2tf(p1));
                }
                ps += __shfl_xor_sync(0xffffffffu, ps, 1);
                ps += __shfl_xor_sync(0xffffffffu, ps, 2);
                lrow[hf] = lrow[hf] * corr + ps;
                mrow[hf] = mn;
#pragma unroll
                for (int ot = 0; ot < 16; ot++) {
                    Oacc[ot][2 * hf] *= corr;
                    Oacc[ot][2 * hf + 1] *= corr;
                }
            }
            __syncwarp();  // P rows are warp-private

            // ---- PV: O(16x128) += P(16x64) @ V(64x128) ----
#pragma unroll 2
            for (int ks = 0; ks < 8; ks++) {
                int k0 = ks * 8;
                const uint32_t* pr = Ps + (mrow0 + group) * AT_PST + k0 + tg;
                uint32_t a0 = pr[0];
                uint32_t a1 = pr[8 * AT_PST];
                uint32_t a2 = pr[4];
                uint32_t a3 = pr[8 * AT_PST + 4];
#pragma unroll
                for (int ot = 0; ot < 16; ot++) {
                    const uint32_t* vr = Vsp + (k0 + tg) * AT_KST + ot * 8 + group;
                    mma_tf32(Oacc[ot], a0, a1, a2, a3, vr[0], vr[4 * AT_KST]);
                }
            }
        }
    }

    // ---- write out ----
    {
        int r0 = mrow0 + group;
        float inv0 = 1.f / lrow[0];
        float inv1 = 1.f / lrow[1];
        int tok0 = (b << 10) + (qt << 7) + r0;
#pragma unroll
        for (int ot = 0; ot < 16; ot++) {
            int col = ot * 8 + 2 * tg;
            float2 v01 = make_float2(Oacc[ot][0] * inv0, Oacc[ot][1] * inv0);
            float2 v23 = make_float2(Oacc[ot][2] * inv1, Oacc[ot][3] * inv1);
            *(float2*)(ob + (size_t)tok0 * (NH * HD) + (h << 7) + col) = v01;
            *(float2*)(ob + (size_t)(tok0 + 8) * (NH * HD) + (h << 7) + col) = v23;
        }
    }
}

// ---------------- launch ----------------
extern "C" void kernel_launch(void* const* d_in, const int* in_sizes, int n_in,
                              void* d_out, int out_size) {
    const float* x  = (const float*)d_in[0];
    const float* wq = (const float*)d_in[1];
    const float* wk = (const float*)d_in[2];
    const float* wv = (const float*)d_in[3];
    const float* wo = (const float*)d_in[4];
    const int* positions = (const int*)d_in[7];
    float* out = (float*)d_out;

    float* qb; cudaGetSymbolAddress((void**)&qb, g_q);
    float* kb; cudaGetSymbolAddress((void**)&kb, g_k);
    float* vb; cudaGetSymbolAddress((void**)&vb, g_v);
    float* ab; cudaGetSymbolAddress((void**)&ab, g_attn);

    rope_table_kernel<<<(SEQ * 64 + 255) / 256, 256>>>();

    // QKV projections (tf32 tensor cores)
    {
        dim3 gq(DIMM / 128, T_TOK / 128);
        tf32_gemm<<<gq, 256>>>(x, wq, qb, T_TOK, DIMM, DIMM);
        dim3 gk((NKV * HD) / 128, T_TOK / 128);
        tf32_gemm<<<gk, 256>>>(x, wk, kb, T_TOK, NKV * HD, DIMM);
        tf32_gemm<<<gk, 256>>>(x, wv, vb, T_TOK, NKV * HD, DIMM);
    }

    // RoPE: Q raw fp32; K rounded to tf32 grid (enables cp.async w/o conversion)
    rope_apply_kernel<<<T_TOK, 512>>>(qb, positions, NH, 0);
    rope_apply_kernel<<<T_TOK, 512>>>(kb, positions, NKV, 1);
    // V rounded to tf32 grid
    round_v_kernel<<<2048, 256>>>(vb);

    // attention (tf32 tensor cores, cp.async pipelined)
    {
        size_t smem = (size_t)AT_SMEM_WORDS * sizeof(uint32_t);  // ~166 KB
        cudaFuncSetAttribute(attn5_kernel, cudaFuncAttributeMaxDynamicSharedMemorySize, (int)smem);
        dim3 ga(8, BATCH * NH);
        attn5_kernel<<<ga, 256, smem>>>(qb, kb, vb, ab);
    }

    // output projection
    {
        dim3 go(DIMM / 128, T_TOK / 128);
        tf32_gemm<<<go, 256>>>(ab, wo, out, T_TOK, DIMM, DIMM);
    }
}

// round 14
// speedup vs baseline: 1.5029x; 1.5029x over previous
#include <cuda_runtime.h>
#include <cuda_bf16.h>
#include <math.h>
#include <stdint.h>

// Problem constants
#define T_TOK   8192
#define DIMM    2048
#define NH      16
#define NKV     8
#define HD      128
#define SEQ     1024
#define BATCH   8

// ---------------- scratch (device globals) ----------------
// qkv layout per token row (stride 4096): [0,2048)=Q heads, [2048,3072)=K, [3072,4096)=V
__device__ float g_qkv[T_TOK * (size_t)4096];        // 128 MB
__device__ float g_attn[T_TOK * (size_t)(NH * HD)];  // 64 MB (attention out, tf32-rounded)
__device__ float g_xr[T_TOK * (size_t)DIMM];         // 64 MB (x rounded)
__device__ float g_wqkv[(size_t)DIMM * 4096];        // 32 MB (packed+rounded wq|wk|wv)
__device__ float g_wor[(size_t)DIMM * DIMM];         // 16 MB (wo rounded)
__device__ float g_cos[SEQ * 64];
__device__ float g_sin[SEQ * 64];

__device__ __forceinline__ uint32_t f2tf(float x) {
    uint32_t r;
    asm("cvt.rna.tf32.f32 %0, %1;" : "=r"(r) : "f"(x));
    return r;
}
__device__ __forceinline__ float rtf(float x) { return __uint_as_float(f2tf(x)); }

__device__ __forceinline__ void mma_tf32(float* c,
                                         uint32_t a0, uint32_t a1, uint32_t a2, uint32_t a3,
                                         uint32_t b0, uint32_t b1) {
    asm volatile(
        "mma.sync.aligned.m16n8k8.row.col.f32.tf32.tf32.f32 "
        "{%0,%1,%2,%3}, {%4,%5,%6,%7}, {%8,%9}, {%0,%1,%2,%3};\n"
        : "+f"(c[0]), "+f"(c[1]), "+f"(c[2]), "+f"(c[3])
        : "r"(a0), "r"(a1), "r"(a2), "r"(a3), "r"(b0), "r"(b1));
}

__device__ __forceinline__ void cp_async16(uint32_t smem_addr, const void* gptr) {
    asm volatile("cp.async.cg.shared.global [%0], [%1], 16;\n" ::
                 "r"(smem_addr), "l"(gptr));
}
__device__ __forceinline__ void cp_async_commit() {
    asm volatile("cp.async.commit_group;\n" ::: "memory");
}
template <int N>
__device__ __forceinline__ void cp_async_wait() {
    asm volatile("cp.async.wait_group %0;\n" :: "n"(N) : "memory");
}

// ---------------- RoPE table ----------------
__global__ void rope_table_kernel() {
    int idx = blockIdx.x * blockDim.x + threadIdx.x;
    if (idx >= SEQ * 64) return;
    int pos = idx >> 6;
    int f = idx & 63;
    double inv = pow(10000.0, -(double)f / 64.0);
    double ang = (double)pos * inv;
    g_cos[idx] = (float)cos(ang);
    g_sin[idx] = (float)sin(ang);
}

// ---------------- RoPE apply (strided rows; optional tf32 RNA rounding) ----------------
__global__ void rope_apply_kernel(float* __restrict__ buf, const int* __restrict__ positions,
                                  int heads, int rowstride, int round_tf32) {
    int t = blockIdx.x;
    int pos = positions[t];
    int npairs = heads * 64;
    for (int i = threadIdx.x; i < npairs; i += blockDim.x) {
        int h = i >> 6;
        int f = i & 63;
        float c = g_cos[pos * 64 + f];
        float s = g_sin[pos * 64 + f];
        float* p = buf + (size_t)t * rowstride + h * HD + 2 * f;
        float xr = p[0], xi = p[1];
        float o0 = xr * c - xi * s;
        float o1 = xr * s + xi * c;
        if (round_tf32) { o0 = rtf(o0); o1 = rtf(o1); }
        p[0] = o0;
        p[1] = o1;
    }
}

// ---------------- rounding / packing kernels ----------------
__global__ void round_x_kernel(const float* __restrict__ x, float* __restrict__ out) {
    int i = blockIdx.x * blockDim.x + threadIdx.x;   // 8192*512 = T_TOK*DIMM/4
    float4 v = ((const float4*)x)[i];
    v.x = rtf(v.x); v.y = rtf(v.y); v.z = rtf(v.z); v.w = rtf(v.w);
    ((float4*)out)[i] = v;
}

__global__ void pack_wqkv_kernel(const float* __restrict__ wq, const float* __restrict__ wk,
                                 const float* __restrict__ wv, float* __restrict__ out) {
    int i = blockIdx.x * blockDim.x + threadIdx.x;   // 2048*1024 f4
    int k = i >> 10;
    int c4 = (i & 1023) * 4;
    float4 v;
    if (c4 < 2048)      v = *(const float4*)(wq + (size_t)k * 2048 + c4);
    else if (c4 < 3072) v = *(const float4*)(wk + (size_t)k * 1024 + (c4 - 2048));
    else                v = *(const float4*)(wv + (size_t)k * 1024 + (c4 - 3072));
    v.x = rtf(v.x); v.y = rtf(v.y); v.z = rtf(v.z); v.w = rtf(v.w);
    *(float4*)(out + (size_t)k * 4096 + c4) = v;
}

__global__ void round_wo_kernel(const float* __restrict__ wo, float* __restrict__ out) {
    int i = blockIdx.x * blockDim.x + threadIdx.x;   // 2048*512 f4
    float4 v = ((const float4*)wo)[i];
    v.x = rtf(v.x); v.y = rtf(v.y); v.z = rtf(v.z); v.w = rtf(v.w);
    ((float4*)out)[i] = v;
}

__global__ void round_v_kernel(float* __restrict__ qkv) {
    int i = blockIdx.x * blockDim.x + threadIdx.x;   // 8192*256 f4 (V slice)
    int r = i >> 8;
    int c4 = (i & 255) * 4;
    float* p = qkv + (size_t)r * 4096 + 3072 + c4;
    float4 v = *(float4*)p;
    v.x = rtf(v.x); v.y = rtf(v.y); v.z = rtf(v.z); v.w = rtf(v.w);
    *(float4*)p = v;
}

// ---------------- TF32 GEMM, cp.async 4-stage pipeline ----------------
// C[M,N] = A[M,K] @ B[K,N]; A,B pre-rounded to tf32 grid (raw bits consumed).
// BM=BN=128, BK=16, 256 threads = 8 warps (2x4), warp tile 64x32, 4x4 m16n8k8.
// A smem row-major stride 20 (banks: group*20+tg mod 32 -> 32 distinct).
// B smem row-major stride 136 (banks: tg*8+group -> 32 distinct).
#define G2_AST 20
#define G2_BST 136
#define G2_ASTG (128 * G2_AST)          // 2560 words
#define G2_BSTG (16 * G2_BST)           // 2176 words
#define G2_STGW (G2_ASTG + G2_BSTG)     // 4736 words
#define G2_STAGES 4
#define G2_SMEM_BYTES (G2_STAGES * G2_STGW * 4)   // 75776 B

__global__ __launch_bounds__(256, 2) void gemm2(const float* __restrict__ A,
                                                const float* __restrict__ B,
                                                float* __restrict__ C,
                                                int M, int N, int K) {
    extern __shared__ uint32_t sm2[];
    int tid = threadIdx.x;
    int warp = tid >> 5, lane = tid & 31;
    int wy = warp >> 2, wx = warp & 3;
    int group = lane >> 2, tg = lane & 3;
    int bm = blockIdx.y * 128, bn = blockIdx.x * 128;

    // cp.async mapping: A: 512 chunks of 16B (128 rows x 4 chunks); B: 512 chunks (16 rows x 32)
    int a_m = tid >> 2;              // 0..63 (+64 for second)
    int a_k = (tid & 3) * 4;
    int b_k = tid >> 5;              // 0..7 (+8 for second)
    int b_n = (tid & 31) * 4;

    const float* Ag = A + (size_t)(bm + a_m) * K + a_k;
    const float* Bg = B + bn + b_n;

    uint32_t smem_u32 = (uint32_t)__cvta_generic_to_shared((void*)sm2);

    int NT = K >> 4;

    // prologue: stages 0..2
#pragma unroll
    for (int s = 0; s < G2_STAGES - 1; s++) {
        int k0 = s * 16;
        uint32_t sb = smem_u32 + s * G2_STGW * 4;
        cp_async16(sb + (a_m * G2_AST + a_k) * 4, Ag + k0);
        cp_async16(sb + ((a_m + 64) * G2_AST + a_k) * 4, Ag + 64 * (size_t)K + k0);
        uint32_t bb = sb + G2_ASTG * 4;
        cp_async16(bb + (b_k * G2_BST + b_n) * 4, Bg + (size_t)(k0 + b_k) * N);
        cp_async16(bb + ((b_k + 8) * G2_BST + b_n) * 4, Bg + (size_t)(k0 + b_k + 8) * N);
        cp_async_commit();
    }

    float acc[4][4][4];
#pragma unroll
    for (int mt = 0; mt < 4; mt++)
#pragma unroll
        for (int nt = 0; nt < 4; nt++)
#pragma unroll
            for (int r = 0; r < 4; r++) acc[mt][nt][r] = 0.f;

#pragma unroll 1
    for (int kt = 0; kt < NT; kt++) {
        int s = kt & (G2_STAGES - 1);
        cp_async_wait<2>();      // stage kt arrived (one commit per iter keeps accounting exact)
        __syncthreads();

        // prefetch kt+3 into buffer (kt+3)%4 (freed by the barrier above)
        if (kt + G2_STAGES - 1 < NT) {
            int sp = (kt + G2_STAGES - 1) & (G2_STAGES - 1);
            int k0 = (kt + G2_STAGES - 1) * 16;
            uint32_t sb = smem_u32 + sp * G2_STGW * 4;
            cp_async16(sb + (a_m * G2_AST + a_k) * 4, Ag + k0);
            cp_async16(sb + ((a_m + 64) * G2_AST + a_k) * 4, Ag + 64 * (size_t)K + k0);
            uint32_t bb = sb + G2_ASTG * 4;
            cp_async16(bb + (b_k * G2_BST + b_n) * 4, Bg + (size_t)(k0 + b_k) * N);
            cp_async16(bb + ((b_k + 8) * G2_BST + b_n) * 4, Bg + (size_t)(k0 + b_k + 8) * N);
        }
        cp_async_commit();       // commit every iteration (possibly empty group)

        const uint32_t* As = sm2 + s * G2_STGW;
        const uint32_t* Bs = As + G2_ASTG;

#pragma unroll
        for (int ks = 0; ks < 2; ks++) {
            int k0 = ks * 8;
            uint32_t afr[4][4], bfr[4][2];
#pragma unroll
            for (int nt = 0; nt < 4; nt++) {
                int nb = wx * 32 + nt * 8 + group;
                bfr[nt][0] = Bs[(k0 + tg) * G2_BST + nb];
                bfr[nt][1] = Bs[(k0 + tg + 4) * G2_BST + nb];
            }
#pragma unroll
            for (int mt = 0; mt < 4; mt++) {
                int mb = wy * 64 + mt * 16 + group;
                afr[mt][0] = As[mb * G2_AST + k0 + tg];
                afr[mt][1] = As[(mb + 8) * G2_AST + k0 + tg];
                afr[mt][2] = As[mb * G2_AST + k0 + tg + 4];
                afr[mt][3] = As[(mb + 8) * G2_AST + k0 + tg + 4];
            }
#pragma unroll
            for (int mt = 0; mt < 4; mt++)
#pragma unroll
                for (int nt = 0; nt < 4; nt++)
                    mma_tf32(acc[mt][nt], afr[mt][0], afr[mt][1], afr[mt][2], afr[mt][3],
                             bfr[nt][0], bfr[nt][1]);
        }
    }

    // epilogue
#pragma unroll
    for (int mt = 0; mt < 4; mt++) {
#pragma unroll
        for (int nt = 0; nt < 4; nt++) {
            int row = bm + wy * 64 + mt * 16 + group;
            int col = bn + wx * 32 + nt * 8 + tg * 2;
            float2 v01 = make_float2(acc[mt][nt][0], acc[mt][nt][1]);
            float2 v23 = make_float2(acc[mt][nt][2], acc[mt][nt][3]);
            *(float2*)(C + (size_t)row * N + col) = v01;
            *(float2*)(C + (size_t)(row + 8) * N + col) = v23;
        }
    }
}

// ---------------- Flash attention (R9-validated), reading packed qkv ----------------
#define AT_KST 132
#define AT_PST 68
#define KVBUF  (64 * AT_KST)
#define AT_SMEM_WORDS (4 * KVBUF + 128 * AT_PST)

__global__ __launch_bounds__(256, 1) void attn5_kernel(const float* __restrict__ qkv,
                                                       float* __restrict__ ob) {
    extern __shared__ uint32_t smw[];
    uint32_t* Ps = smw + 4 * KVBUF;

    const float scale = 0.08838834764831845f;
    int qt = 7 - blockIdx.x;
    int bh = blockIdx.y;
    int b = bh >> 4;
    int h = bh & 15;
    int kvh = h >> 1;

    int tid = threadIdx.x;
    int warp = tid >> 5, lane = tid & 31;
    int group = lane >> 2, tg = lane & 3;
    int mrow0 = warp * 16;

    int sr = tid >> 5;
    int sc4 = (tid & 31) * 4;
    const size_t kvstride = 4096;
    const float* kvb_base_k = qkv + (size_t)(b << 10) * kvstride + 2048 + (kvh << 7) + sc4;
    const float* kvb_base_v = qkv + (size_t)(b << 10) * kvstride + 3072 + (kvh << 7) + sc4;

    uint32_t smem_base_u32 = (uint32_t)__cvta_generic_to_shared((void*)smw);

    int ntiles = 2 * qt + 2;

    // prologue: stage tile 0 into buffer 0
    {
#pragma unroll
        for (int j = 0; j < 8; j++) {
            int r = sr + j * 8;
            uint32_t kdst = smem_base_u32 + (0 * 2 * KVBUF + r * AT_KST + sc4) * 4;
            uint32_t vdst = smem_base_u32 + ((0 * 2 + 1) * KVBUF + r * AT_KST + sc4) * 4;
            cp_async16(kdst, kvb_base_k + (size_t)r * kvstride);
            cp_async16(vdst, kvb_base_v + (size_t)r * kvstride);
        }
        cp_async_commit();
    }

    // Q into registers (scaled, rounded)
    uint32_t qA[64];
    {
        int tok0 = (b << 10) + (qt << 7) + mrow0 + group;
        const float* q0 = qkv + (size_t)tok0 * kvstride + (h << 7) + tg;
        const float* q1 = q0 + 8 * kvstride;
#pragma unroll
        for (int m = 0; m < 32; m++) {
            qA[m] = f2tf(q0[4 * m] * scale);
            qA[32 + m] = f2tf(q1[4 * m] * scale);
        }
    }

    float Oacc[16][4];
#pragma unroll
    for (int ot = 0; ot < 16; ot++)
#pragma unroll
        for (int r = 0; r < 4; r++) Oacc[ot][r] = 0.f;
    float mrow[2] = {-INFINITY, -INFINITY};
    float lrow[2] = {0.f, 0.f};

    for (int kt = 0; kt < ntiles; kt++) {
        int p = kt & 1;
        cp_async_wait<0>();
        __syncthreads();

        if (kt + 1 < ntiles) {
            int q = p ^ 1;
            int r0 = (kt + 1) * 64;
#pragma unroll
            for (int j = 0; j < 8; j++) {
                int r = sr + j * 8;
                uint32_t kdst = smem_base_u32 + (q * 2 * KVBUF + r * AT_KST + sc4) * 4;
                uint32_t vdst = smem_base_u32 + ((q * 2 + 1) * KVBUF + r * AT_KST + sc4) * 4;
                cp_async16(kdst, kvb_base_k + (size_t)(r0 + r) * kvstride);
                cp_async16(vdst, kvb_base_v + (size_t)(r0 + r) * kvstride);
            }
            cp_async_commit();
        }

        const uint32_t* Ksp = smw + p * 2 * KVBUF;
        const uint32_t* Vsp = Ksp + KVBUF;

        bool active = (kt << 6) <= (qt << 7) + mrow0 + 15;
        if (active) {
            float sacc[8][4];
#pragma unroll
            for (int nt = 0; nt < 8; nt++)
#pragma unroll
                for (int r = 0; r < 4; r++) sacc[nt][r] = 0.f;

#pragma unroll 4
            for (int ks = 0; ks < 16; ks++) {
                uint32_t a0 = qA[2 * ks];
                uint32_t a1 = qA[32 + 2 * ks];
                uint32_t a2 = qA[2 * ks + 1];
                uint32_t a3 = qA[32 + 2 * ks + 1];
                int k0 = ks * 8;
#pragma unroll
                for (int nt = 0; nt < 8; nt++) {
                    const uint32_t* kr = Ksp + (nt * 8 + group) * AT_KST + k0 + tg;
                    mma_tf32(sacc[nt], a0, a1, a2, a3, kr[0], kr[4]);
                }
            }

            if (kt >= 2 * qt) {
                int qp = (qt << 7) + mrow0 + group;
#pragma unroll
                for (int nt = 0; nt < 8; nt++) {
                    int kp = (kt << 6) + nt * 8 + 2 * tg;
                    if (kp > qp) sacc[nt][0] = -INFINITY;
                    if (kp + 1 > qp) sacc[nt][1] = -INFINITY;
                    if (kp > qp + 8) sacc[nt][2] = -INFINITY;
                    if (kp + 1 > qp + 8) sacc[nt][3] = -INFINITY;
                }
            }

#pragma unroll
            for (int hf = 0; hf < 2; hf++) {
                float tm = -INFINITY;
#pragma unroll
                for (int nt = 0; nt < 8; nt++) {
                    tm = fmaxf(tm, sacc[nt][2 * hf]);
                    tm = fmaxf(tm, sacc[nt][2 * hf + 1]);
                }
                tm = fmaxf(tm, __shfl_xor_sync(0xffffffffu, tm, 1));
                tm = fmaxf(tm, __shfl_xor_sync(0xffffffffu, tm, 2));
                float mn = fmaxf(mrow[hf], tm);
                float corr = __expf(mrow[hf] - mn);
                float ps = 0.f;
                int row = mrow0 + group + hf * 8;
#pragma unroll
                for (int nt = 0; nt < 8; nt++) {
                    float p0 = __expf(sacc[nt][2 * hf] - mn);
                    float p1 = __expf(sacc[nt][2 * hf + 1] - mn);
                    ps += p0 + p1;
                    *(uint2*)&Ps[row * AT_PST + nt * 8 + 2 * tg] = make_uint2(f2tf(p0), f2tf(p1));
                }
                ps += __shfl_xor_sync(0xffffffffu, ps, 1);
                ps += __shfl_xor_sync(0xffffffffu, ps, 2);
                lrow[hf] = lrow[hf] * corr + ps;
                mrow[hf] = mn;
#pragma unroll
                for (int ot = 0; ot < 16; ot++) {
                    Oacc[ot][2 * hf] *= corr;
                    Oacc[ot][2 * hf + 1] *= corr;
                }
            }
            __syncwarp();

#pragma unroll 2
            for (int ks = 0; ks < 8; ks++) {
                int k0 = ks * 8;
                const uint32_t* pr = Ps + (mrow0 + group) * AT_PST + k0 + tg;
                uint32_t a0 = pr[0];
                uint32_t a1 = pr[8 * AT_PST];
                uint32_t a2 = pr[4];
                uint32_t a3 = pr[8 * AT_PST + 4];
#pragma unroll
                for (int ot = 0; ot < 16; ot++) {
                    const uint32_t* vr = Vsp + (k0 + tg) * AT_KST + ot * 8 + group;
                    mma_tf32(Oacc[ot], a0, a1, a2, a3, vr[0], vr[4 * AT_KST]);
                }
            }
        }
    }

    // write out, RNA-rounded so wo-GEMM can consume raw bits as tf32
    {
        int r0 = mrow0 + group;
        float inv0 = 1.f / lrow[0];
        float inv1 = 1.f / lrow[1];
        int tok0 = (b << 10) + (qt << 7) + r0;
#pragma unroll
        for (int ot = 0; ot < 16; ot++) {
            int col = ot * 8 + 2 * tg;
            float2 v01 = make_float2(rtf(Oacc[ot][0] * inv0), rtf(Oacc[ot][1] * inv0));
            float2 v23 = make_float2(rtf(Oacc[ot][2] * inv1), rtf(Oacc[ot][3] * inv1));
            *(float2*)(ob + (size_t)tok0 * (NH * HD) + (h << 7) + col) = v01;
            *(float2*)(ob + (size_t)(tok0 + 8) * (NH * HD) + (h << 7) + col) = v23;
        }
    }
}

// ---------------- launch ----------------
extern "C" void kernel_launch(void* const* d_in, const int* in_sizes, int n_in,
                              void* d_out, int out_size) {
    const float* x  = (const float*)d_in[0];
    const float* wq = (const float*)d_in[1];
    const float* wk = (const float*)d_in[2];
    const float* wv = (const float*)d_in[3];
    const float* wo = (const float*)d_in[4];
    const int* positions = (const int*)d_in[7];
    float* out = (float*)d_out;

    float* qkv; cudaGetSymbolAddress((void**)&qkv, g_qkv);
    float* ab;  cudaGetSymbolAddress((void**)&ab, g_attn);
    float* xr;  cudaGetSymbolAddress((void**)&xr, g_xr);
    float* wqkv;cudaGetSymbolAddress((void**)&wqkv, g_wqkv);
    float* wor; cudaGetSymbolAddress((void**)&wor, g_wor);

    rope_table_kernel<<<(SEQ * 64 + 255) / 256, 256>>>();

    // pre-round operands to tf32 grid
    round_x_kernel<<<8192, 512>>>(x, xr);
    pack_wqkv_kernel<<<4096, 512>>>(wq, wk, wv, wqkv);
    round_wo_kernel<<<2048, 512>>>(wo, wor);

    cudaFuncSetAttribute(gemm2, cudaFuncAttributeMaxDynamicSharedMemorySize, G2_SMEM_BYTES);

    // fused QKV projection: [8192,2048] @ [2048,4096]
    {
        dim3 g(4096 / 128, T_TOK / 128);
        gemm2<<<g, 256, G2_SMEM_BYTES>>>(xr, wqkv, qkv, T_TOK, 4096, DIMM);
    }

    // RoPE: Q raw fp32 (rounded at attention load); K rounded for cp.async consumption
    rope_apply_kernel<<<T_TOK, 512>>>(qkv, positions, NH, 4096, 0);
    rope_apply_kernel<<<T_TOK, 512>>>(qkv + 2048, positions, NKV, 4096, 1);
    round_v_kernel<<<4096, 512>>>(qkv);

    // attention
    {
        size_t smem = (size_t)AT_SMEM_WORDS * sizeof(uint32_t);
        cudaFuncSetAttribute(attn5_kernel, cudaFuncAttributeMaxDynamicSharedMemorySize, (int)smem);
        dim3 ga(8, BATCH * NH);
        attn5_kernel<<<ga, 256, smem>>>(qkv, ab);
    }

    // output projection: [8192,2048] @ [2048,2048]
    {
        dim3 g(DIMM / 128, T_TOK / 128);
        gemm2<<<g, 256, G2_SMEM_BYTES>>>(ab, wor, out, T_TOK, DIMM, DIMM);
    }
}

// round 17
// speedup vs baseline: 2.0427x; 1.3591x over previous
#include <cuda_runtime.h>
#include <cuda_fp16.h>
#include <math.h>
#include <stdint.h>

// Problem constants
#define T_TOK   8192
#define DIMM    2048
#define NH      16
#define NKV     8
#define HD      128
#define SEQ     1024
#define BATCH   8

// ---------------- scratch (device globals) ----------------
// qkv layout per token row (stride 4096): [0,2048)=Q, [2048,3072)=K, [3072,4096)=V
__device__ float  g_qkv[T_TOK * (size_t)4096];          // 128 MB (fp32, gemm output)
__device__ __half g_attnh[T_TOK * (size_t)(NH * HD)];   // 32 MB (attention out, half)
__device__ __half g_xh[T_TOK * (size_t)DIMM];           // 32 MB (x as half)
__device__ __half g_wqkvT[(size_t)4096 * DIMM];         // 16 MB ([N][K] half, packed wq|wk|wv)
__device__ __half g_woT[(size_t)DIMM * DIMM];           // 8 MB  ([N][K] half)
__device__ float  g_cos[SEQ * 64];
__device__ float  g_sin[SEQ * 64];

__device__ __forceinline__ uint32_t f2tf(float x) {
    uint32_t r;
    asm("cvt.rna.tf32.f32 %0, %1;" : "=r"(r) : "f"(x));
    return r;
}
__device__ __forceinline__ float rtf(float x) { return __uint_as_float(f2tf(x)); }

__device__ __forceinline__ void mma_tf32(float* c,
                                         uint32_t a0, uint32_t a1, uint32_t a2, uint32_t a3,
                                         uint32_t b0, uint32_t b1) {
    asm volatile(
        "mma.sync.aligned.m16n8k8.row.col.f32.tf32.tf32.f32 "
        "{%0,%1,%2,%3}, {%4,%5,%6,%7}, {%8,%9}, {%0,%1,%2,%3};\n"
        : "+f"(c[0]), "+f"(c[1]), "+f"(c[2]), "+f"(c[3])
        : "r"(a0), "r"(a1), "r"(a2), "r"(a3), "r"(b0), "r"(b1));
}

__device__ __forceinline__ void mma_f16(float* c,
                                        uint32_t a0, uint32_t a1, uint32_t a2, uint32_t a3,
                                        uint32_t b0, uint32_t b1) {
    asm volatile(
        "mma.sync.aligned.m16n8k16.row.col.f32.f16.f16.f32 "
        "{%0,%1,%2,%3}, {%4,%5,%6,%7}, {%8,%9}, {%0,%1,%2,%3};\n"
        : "+f"(c[0]), "+f"(c[1]), "+f"(c[2]), "+f"(c[3])
        : "r"(a0), "r"(a1), "r"(a2), "r"(a3), "r"(b0), "r"(b1));
}

__device__ __forceinline__ void cp_async16(uint32_t smem_addr, const void* gptr) {
    asm volatile("cp.async.cg.shared.global [%0], [%1], 16;\n" ::
                 "r"(smem_addr), "l"(gptr));
}
__device__ __forceinline__ void cp_async_commit() {
    asm volatile("cp.async.commit_group;\n" ::: "memory");
}
template <int N>
__device__ __forceinline__ void cp_async_wait() {
    asm volatile("cp.async.wait_group %0;\n" :: "n"(N) : "memory");
}

// ---------------- RoPE table ----------------
__global__ void rope_table_kernel() {
    int idx = blockIdx.x * blockDim.x + threadIdx.x;
    if (idx >= SEQ * 64) return;
    int pos = idx >> 6;
    int f = idx & 63;
    double inv = pow(10000.0, -(double)f / 64.0);
    double ang = (double)pos * inv;
    g_cos[idx] = (float)cos(ang);
    g_sin[idx] = (float)sin(ang);
}

// ---------------- RoPE apply (strided rows; optional tf32 RNA rounding) ----------------
__global__ void rope_apply_kernel(float* __restrict__ buf, const int* __restrict__ positions,
                                  int heads, int rowstride, int round_tf32) {
    int t = blockIdx.x;
    int pos = positions[t];
    int npairs = heads * 64;
    for (int i = threadIdx.x; i < npairs; i += blockDim.x) {
        int h = i >> 6;
        int f = i & 63;
        float c = g_cos[pos * 64 + f];
        float s = g_sin[pos * 64 + f];
        float* p = buf + (size_t)t * rowstride + h * HD + 2 * f;
        float xr = p[0], xi = p[1];
        float o0 = xr * c - xi * s;
        float o1 = xr * s + xi * c;
        if (round_tf32) { o0 = rtf(o0); o1 = rtf(o1); }
        p[0] = o0;
        p[1] = o1;
    }
}

// ---------------- conversion / packing kernels ----------------
__global__ void x_to_half(const float* __restrict__ x, __half* __restrict__ out) {
    int i = blockIdx.x * blockDim.x + threadIdx.x;   // over float4: T*D/4
    float4 v = ((const float4*)x)[i];
    __half2 h0 = __floats2half2_rn(v.x, v.y);
    __half2 h1 = __floats2half2_rn(v.z, v.w);
    ((__half2*)out)[2 * i] = h0;
    ((__half2*)out)[2 * i + 1] = h1;
}

// transpose+pack: out[n][k] = {wq|wk|wv}(k, n'), half. grid (K/32, 4096/32), block (32,8)
__global__ void transpose_pack_wqkv(const float* __restrict__ wq, const float* __restrict__ wk,
                                    const float* __restrict__ wv, __half* __restrict__ out) {
    __shared__ float tile[32][33];
    int k0 = blockIdx.x * 32, n0 = blockIdx.y * 32;
    int tx = threadIdx.x, ty = threadIdx.y;
    const float* src; int ld; int nc;
    if (n0 < 2048)      { src = wq; ld = 2048; nc = n0; }
    else if (n0 < 3072) { src = wk; ld = 1024; nc = n0 - 2048; }
    else                { src = wv; ld = 1024; nc = n0 - 3072; }
#pragma unroll
    for (int j = 0; j < 4; j++)
        tile[ty + 8 * j][tx] = src[(size_t)(k0 + ty + 8 * j) * ld + nc + tx];
    __syncthreads();
#pragma unroll
    for (int j = 0; j < 4; j++)
        out[(size_t)(n0 + ty + 8 * j) * DIMM + k0 + tx] = __float2half(tile[tx][ty + 8 * j]);
}

// transpose wo: out[n][k] = wo(k, n), half. grid (64, 64), block (32,8)
__global__ void transpose_wo(const float* __restrict__ w, __half* __restrict__ out) {
    __shared__ float tile[32][33];
    int k0 = blockIdx.x * 32, n0 = blockIdx.y * 32;
    int tx = threadIdx.x, ty = threadIdx.y;
#pragma unroll
    for (int j = 0; j < 4; j++)
        tile[ty + 8 * j][tx] = w[(size_t)(k0 + ty + 8 * j) * DIMM + n0 + tx];
    __syncthreads();
#pragma unroll
    for (int j = 0; j < 4; j++)
        out[(size_t)(n0 + ty + 8 * j) * DIMM + k0 + tx] = __float2half(tile[tx][ty + 8 * j]);
}

__global__ void round_v_kernel(float* __restrict__ qkv) {
    int i = blockIdx.x * blockDim.x + threadIdx.x;   // 8192*256 f4 (V slice)
    int r = i >> 8;
    int c4 = (i & 255) * 4;
    float* p = qkv + (size_t)r * 4096 + 3072 + c4;
    float4 v = *(float4*)p;
    v.x = rtf(v.x); v.y = rtf(v.y); v.z = rtf(v.z); v.w = rtf(v.w);
    *(float4*)p = v;
}

// ---------------- FP16 GEMM, cp.async 4-stage pipeline ----------------
// C[M,N](fp32) = A[M,K](half,row) @ Bt[N,K](half, pre-transposed).
// BM=BN=128, BK=32, 256 threads = 8 warps (2x4), warp tile 64x32, mma m16n8k16.
// smem rows: 32 halves = 16 words, padded to 20 words -> fragment banks (20g+tg) all distinct.
#define H_ST 20
#define H_TILE (128 * H_ST)            // 2560 words per operand tile
#define H_STGW (2 * H_TILE)            // 5120 words per stage
#define H_STAGES 4
#define H_SMEM_BYTES (H_STAGES * H_STGW * 4)   // 81920 B

__global__ __launch_bounds__(256, 2) void gemm_h(const __half* __restrict__ A,
                                                 const __half* __restrict__ Bt,
                                                 float* __restrict__ C,
                                                 int M, int N, int K) {
    extern __shared__ uint32_t smh[];
    int tid = threadIdx.x;
    int warp = tid >> 5, lane = tid & 31;
    int wy = warp >> 2, wx = warp & 3;
    int group = lane >> 2, tg = lane & 3;
    int bm = blockIdx.y * 128, bn = blockIdx.x * 128;

    // staging map: per operand 512 chunks of 16B (128 rows x 4); thread does 2 contiguous
    int s_m = tid >> 1;               // row 0..127
    int s_c = (tid & 1) * 2;          // chunk base 0 or 2 (each chunk = 8 halves = 4 words)

    const __half* Ag = A + (size_t)(bm + s_m) * K + s_c * 8;
    const __half* Bg = Bt + (size_t)(bn + s_m) * K + s_c * 8;

    uint32_t smem_u32 = (uint32_t)__cvta_generic_to_shared((void*)smh);
    uint32_t a_dst = smem_u32 + (s_m * H_ST + s_c * 4) * 4;
    uint32_t b_dst = a_dst + H_TILE * 4;

    int NT = K >> 5;

    // prologue: stages 0..2
#pragma unroll
    for (int s = 0; s < H_STAGES - 1; s++) {
        int k0 = s * 32;
        uint32_t so = s * H_STGW * 4;
        cp_async16(a_dst + so, Ag + k0);
        cp_async16(a_dst + so + 16, Ag + k0 + 8);
        cp_async16(b_dst + so, Bg + k0);
        cp_async16(b_dst + so + 16, Bg + k0 + 8);
        cp_async_commit();
    }

    float acc[4][4][4];
#pragma unroll
    for (int mt = 0; mt < 4; mt++)
#pragma unroll
        for (int nt = 0; nt < 4; nt++)
#pragma unroll
            for (int r = 0; r < 4; r++) acc[mt][nt][r] = 0.f;

#pragma unroll 1
    for (int kt = 0; kt < NT; kt++) {
        int s = kt & (H_STAGES - 1);
        cp_async_wait<2>();
        __syncthreads();

        if (kt + H_STAGES - 1 < NT) {
            int sp = (kt + H_STAGES - 1) & (H_STAGES - 1);
            int k0 = (kt + H_STAGES - 1) * 32;
            uint32_t so = sp * H_STGW * 4;
            cp_async16(a_dst + so, Ag + k0);
            cp_async16(a_dst + so + 16, Ag + k0 + 8);
            cp_async16(b_dst + so, Bg + k0);
            cp_async16(b_dst + so + 16, Bg + k0 + 8);
        }
        cp_async_commit();

        const uint32_t* As = smh + s * H_STGW;
        const uint32_t* Bs = As + H_TILE;

#pragma unroll
        for (int ks = 0; ks < 2; ks++) {
            int kw = ks * 8;
            uint32_t afr[4][4], bfr[4][2];
#pragma unroll
            for (int nt = 0; nt < 4; nt++) {
                int nb = wx * 32 + nt * 8 + group;
                bfr[nt][0] = Bs[nb * H_ST + kw + tg];
                bfr[nt][1] = Bs[nb * H_ST + kw + tg + 4];
            }
#pragma unroll
            for (int mt = 0; mt < 4; mt++) {
                int mb = wy * 64 + mt * 16 + group;
                afr[mt][0] = As[mb * H_ST + kw + tg];
                afr[mt][1] = As[(mb + 8) * H_ST + kw + tg];
                afr[mt][2] = As[mb * H_ST + kw + tg + 4];
                afr[mt][3] = As[(mb + 8) * H_ST + kw + tg + 4];
            }
#pragma unroll
            for (int mt = 0; mt < 4; mt++)
#pragma unroll
                for (int nt = 0; nt < 4; nt++)
                    mma_f16(acc[mt][nt], afr[mt][0], afr[mt][1], afr[mt][2], afr[mt][3],
                            bfr[nt][0], bfr[nt][1]);
        }
    }

    // epilogue (fp32 C)
#pragma unroll
    for (int mt = 0; mt < 4; mt++) {
#pragma unroll
        for (int nt = 0; nt < 4; nt++) {
            int row = bm + wy * 64 + mt * 16 + group;
            int col = bn + wx * 32 + nt * 8 + tg * 2;
            float2 v01 = make_float2(acc[mt][nt][0], acc[mt][nt][1]);
            float2 v23 = make_float2(acc[mt][nt][2], acc[mt][nt][3]);
            *(float2*)(C + (size_t)row * N + col) = v01;
            *(float2*)(C + (size_t)(row + 8) * N + col) = v23;
        }
    }
}

// ---------------- Flash attention (tf32, validated), packed qkv in, half out ----------------
#define AT_KST 132
#define AT_PST 68
#define KVBUF  (64 * AT_KST)
#define AT_SMEM_WORDS (4 * KVBUF + 128 * AT_PST)

__global__ __launch_bounds__(256, 1) void attn5_kernel(const float* __restrict__ qkv,
                                                       __half* __restrict__ ob) {
    extern __shared__ uint32_t smw[];
    uint32_t* Ps = smw + 4 * KVBUF;

    const float scale = 0.08838834764831845f;
    int qt = 7 - blockIdx.x;
    int bh = blockIdx.y;
    int b = bh >> 4;
    int h = bh & 15;
    int kvh = h >> 1;

    int tid = threadIdx.x;
    int warp = tid >> 5, lane = tid & 31;
    int group = lane >> 2, tg = lane & 3;
    int mrow0 = warp * 16;

    int sr = tid >> 5;
    int sc4 = (tid & 31) * 4;
    const size_t kvstride = 4096;
    const float* kvb_base_k = qkv + (size_t)(b << 10) * kvstride + 2048 + (kvh << 7) + sc4;
    const float* kvb_base_v = qkv + (size_t)(b << 10) * kvstride + 3072 + (kvh << 7) + sc4;

    uint32_t smem_base_u32 = (uint32_t)__cvta_generic_to_shared((void*)smw);

    int ntiles = 2 * qt + 2;

    // prologue: stage tile 0 into buffer 0
    {
#pragma unroll
        for (int j = 0; j < 8; j++) {
            int r = sr + j * 8;
            uint32_t kdst = smem_base_u32 + (0 * 2 * KVBUF + r * AT_KST + sc4) * 4;
            uint32_t vdst = smem_base_u32 + ((0 * 2 + 1) * KVBUF + r * AT_KST + sc4) * 4;
            cp_async16(kdst, kvb_base_k + (size_t)r * kvstride);
            cp_async16(vdst, kvb_base_v + (size_t)r * kvstride);
        }
        cp_async_commit();
    }

    // Q into registers (scaled, rounded)
    uint32_t qA[64];
    {
        int tok0 = (b << 10) + (qt << 7) + mrow0 + group;
        const float* q0 = qkv + (size_t)tok0 * kvstride + (h << 7) + tg;
        const float* q1 = q0 + 8 * kvstride;
#pragma unroll
        for (int m = 0; m < 32; m++) {
            qA[m] = f2tf(q0[4 * m] * scale);
            qA[32 + m] = f2tf(q1[4 * m] * scale);
        }
    }

    float Oacc[16][4];
#pragma unroll
    for (int ot = 0; ot < 16; ot++)
#pragma unroll
        for (int r = 0; r < 4; r++) Oacc[ot][r] = 0.f;
    float mrow[2] = {-INFINITY, -INFINITY};
    float lrow[2] = {0.f, 0.f};

    for (int kt = 0; kt < ntiles; kt++) {
        int p = kt & 1;
        cp_async_wait<0>();
        __syncthreads();

        if (kt + 1 < ntiles) {
            int q = p ^ 1;
            int r0 = (kt + 1) * 64;
#pragma unroll
            for (int j = 0; j < 8; j++) {
                int r = sr + j * 8;
                uint32_t kdst = smem_base_u32 + (q * 2 * KVBUF + r * AT_KST + sc4) * 4;
                uint32_t vdst = smem_base_u32 + ((q * 2 + 1) * KVBUF + r * AT_KST + sc4) * 4;
                cp_async16(kdst, kvb_base_k + (size_t)(r0 + r) * kvstride);
                cp_async16(vdst, kvb_base_v + (size_t)(r0 + r) * kvstride);
            }
            cp_async_commit();
        }

        const uint32_t* Ksp = smw + p * 2 * KVBUF;
        const uint32_t* Vsp = Ksp + KVBUF;

        bool active = (kt << 6) <= (qt << 7) + mrow0 + 15;
        if (active) {
            float sacc[8][4];
#pragma unroll
            for (int nt = 0; nt < 8; nt++)
#pragma unroll
                for (int r = 0; r < 4; r++) sacc[nt][r] = 0.f;

#pragma unroll 4
            for (int ks = 0; ks < 16; ks++) {
                uint32_t a0 = qA[2 * ks];
                uint32_t a1 = qA[32 + 2 * ks];
                uint32_t a2 = qA[2 * ks + 1];
                uint32_t a3 = qA[32 + 2 * ks + 1];
                int k0 = ks * 8;
#pragma unroll
                for (int nt = 0; nt < 8; nt++) {
                    const uint32_t* kr = Ksp + (nt * 8 + group) * AT_KST + k0 + tg;
                    mma_tf32(sacc[nt], a0, a1, a2, a3, kr[0], kr[4]);
                }
            }

            if (kt >= 2 * qt) {
                int qp = (qt << 7) + mrow0 + group;
#pragma unroll
                for (int nt = 0; nt < 8; nt++) {
                    int kp = (kt << 6) + nt * 8 + 2 * tg;
                    if (kp > qp) sacc[nt][0] = -INFINITY;
                    if (kp + 1 > qp) sacc[nt][1] = -INFINITY;
                    if (kp > qp + 8) sacc[nt][2] = -INFINITY;
                    if (kp + 1 > qp + 8) sacc[nt][3] = -INFINITY;
                }
            }

#pragma unroll
            for (int hf = 0; hf < 2; hf++) {
                float tm = -INFINITY;
#pragma unroll
                for (int nt = 0; nt < 8; nt++) {
                    tm = fmaxf(tm, sacc[nt][2 * hf]);
                    tm = fmaxf(tm, sacc[nt][2 * hf + 1]);
                }
                tm = fmaxf(tm, __shfl_xor_sync(0xffffffffu, tm, 1));
                tm = fmaxf(tm, __shfl_xor_sync(0xffffffffu, tm, 2));
                float mn = fmaxf(mrow[hf], tm);
                float corr = __expf(mrow[hf] - mn);
                float ps = 0.f;
                int row = mrow0 + group + hf * 8;
#pragma unroll
                for (int nt = 0; nt < 8; nt++) {
                    float p0 = __expf(sacc[nt][2 * hf] - mn);
                    float p1 = __expf(sacc[nt][2 * hf + 1] - mn);
                    ps += p0 + p1;
                    *(uint2*)&Ps[row * AT_PST + nt * 8 + 2 * tg] = make_uint2(f2tf(p0), f2tf(p1));
                }
                ps += __shfl_xor_sync(0xffffffffu, ps, 1);
                ps += __shfl_xor_sync(0xffffffffu, ps, 2);
                lrow[hf] = lrow[hf] * corr + ps;
                mrow[hf] = mn;
#pragma unroll
                for (int ot = 0; ot < 16; ot++) {
                    Oacc[ot][2 * hf] *= corr;
                    Oacc[ot][2 * hf + 1] *= corr;
                }
            }
            __syncwarp();

#pragma unroll 2
            for (int ks = 0; ks < 8; ks++) {
                int k0 = ks * 8;
                const uint32_t* pr = Ps + (mrow0 + group) * AT_PST + k0 + tg;
                uint32_t a0 = pr[0];
                uint32_t a1 = pr[8 * AT_PST];
                uint32_t a2 = pr[4];
                uint32_t a3 = pr[8 * AT_PST + 4];
#pragma unroll
                for (int ot = 0; ot < 16; ot++) {
                    const uint32_t* vr = Vsp + (k0 + tg) * AT_KST + ot * 8 + group;
                    mma_tf32(Oacc[ot], a0, a1, a2, a3, vr[0], vr[4 * AT_KST]);
                }
            }
        }
    }

    // write out as half (consumed by fp16 wo-GEMM)
    {
        int r0 = mrow0 + group;
        float inv0 = 1.f / lrow[0];
        float inv1 = 1.f / lrow[1];
        int tok0 = (b << 10) + (qt << 7) + r0;
#pragma unroll
        for (int ot = 0; ot < 16; ot++) {
            int col = ot * 8 + 2 * tg;
            __half2 h01 = __floats2half2_rn(Oacc[ot][0] * inv0, Oacc[ot][1] * inv0);
            __half2 h23 = __floats2half2_rn(Oacc[ot][2] * inv1, Oacc[ot][3] * inv1);
            *(__half2*)(ob + (size_t)tok0 * (NH * HD) + (h << 7) + col) = h01;
            *(__half2*)(ob + (size_t)(tok0 + 8) * (NH * HD) + (h << 7) + col) = h23;
        }
    }
}

// ---------------- launch ----------------
extern "C" void kernel_launch(void* const* d_in, const int* in_sizes, int n_in,
                              void* d_out, int out_size) {
    const float* x  = (const float*)d_in[0];
    const float* wq = (const float*)d_in[1];
    const float* wk = (const float*)d_in[2];
    const float* wv = (const float*)d_in[3];
    const float* wo = (const float*)d_in[4];
    const int* positions = (const int*)d_in[7];
    float* out = (float*)d_out;

    float*  qkv;  cudaGetSymbolAddress((void**)&qkv, g_qkv);
    __half* abh;  cudaGetSymbolAddress((void**)&abh, g_attnh);
    __half* xh;   cudaGetSymbolAddress((void**)&xh, g_xh);
    __half* wqkvT;cudaGetSymbolAddress((void**)&wqkvT, g_wqkvT);
    __half* woT;  cudaGetSymbolAddress((void**)&woT, g_woT);

    rope_table_kernel<<<(SEQ * 64 + 255) / 256, 256>>>();

    // operand conversion / packing
    x_to_half<<<(T_TOK * DIMM / 4) / 256, 256>>>(x, xh);
    {
        dim3 g(DIMM / 32, 4096 / 32);
        transpose_pack_wqkv<<<g, dim3(32, 8)>>>(wq, wk, wv, wqkvT);
    }
    {
        dim3 g(DIMM / 32, DIMM / 32);
        transpose_wo<<<g, dim3(32, 8)>>>(wo, woT);
    }

    cudaFuncSetAttribute(gemm_h, cudaFuncAttributeMaxDynamicSharedMemorySize, H_SMEM_BYTES);

    // fused QKV projection: [8192,2048] @ [2048,4096]
    {
        dim3 g(4096 / 128, T_TOK / 128);
        gemm_h<<<g, 256, H_SMEM_BYTES>>>(xh, wqkvT, qkv, T_TOK, 4096, DIMM);
    }

    // RoPE: Q raw fp32 (rounded at attention load); K rounded for attention cp.async
    rope_apply_kernel<<<T_TOK, 512>>>(qkv, positions, NH, 4096, 0);
    rope_apply_kernel<<<T_TOK, 512>>>(qkv + 2048, positions, NKV, 4096, 1);
    round_v_kernel<<<4096, 512>>>(qkv);

    // attention (tf32 tensor cores, cp.async pipelined), half output
    {
        size_t smem = (size_t)AT_SMEM_WORDS * sizeof(uint32_t);
        cudaFuncSetAttribute(attn5_kernel, cudaFuncAttributeMaxDynamicSharedMemorySize, (int)smem);
        dim3 ga(8, BATCH * NH);
        attn5_kernel<<<ga, 256, smem>>>(qkv, abh);
    }

    // output projection: [8192,2048] @ [2048,2048]
    {
        dim3 g(DIMM / 128, T_TOK / 128);
        gemm_h<<<g, 256, H_SMEM_BYTES>>>(abh, woT, out, T_TOK, DIMM, DIMM);
    }
}